// round 2
// baseline (speedup 1.0000x reference)
#include <cuda_runtime.h>
#include <math_constants.h>

// Prefix-max (cumulative max) along H for x of shape (B=32, C=1, H=1024, W=1024), fp32.
// Layout: x[((b*H)+h)*W + w]. Viewed as float4: W4=256 float4 per row.
// 8192 independent float4-columns (b, w4), scan length H=1024.
//
// Tile: each 1024-thread block owns 8 float4-columns x full H.
//   thread t: c = t & 7 (column-in-tile), chunk = t >> 3 (128 chunks of 8 rows).
//   Each thread: 8 x LDG.128 (coalesced, 512B per warp-load), local prefix-max,
//   block Hillis-Steele max-scan over 128 chunk totals (smem, float4-wide),
//   apply exclusive carry, 8 x STG.128. Single pass, streaming cache hints.

#define H_DIM 1024
#define W4_DIM 256            // 1024 floats / 4
#define COLS4_PER_BLOCK 8
#define CHUNKS 128
#define ROWS_PER_THREAD 8     // H_DIM / CHUNKS

__device__ __forceinline__ float4 fmax4(float4 a, float4 b) {
    return make_float4(fmaxf(a.x, b.x), fmaxf(a.y, b.y),
                       fmaxf(a.z, b.z), fmaxf(a.w, b.w));
}

__global__ __launch_bounds__(1024, 1)
void cummax_kernel(const float4* __restrict__ x, float4* __restrict__ out) {
    const int tid   = threadIdx.x;
    const int c     = tid & (COLS4_PER_BLOCK - 1);   // 0..7
    const int chunk = tid >> 3;                      // 0..127

    const int col4 = blockIdx.x * COLS4_PER_BLOCK + c;   // 0..8191
    const int b    = col4 >> 8;                          // col4 / W4_DIM
    const int w4   = col4 & (W4_DIM - 1);

    // Element (b, h, w4) at b*H*W4 + h*W4 + w4 (float4 units). Max index 8.4M, int ok.
    const int base = b * (H_DIM * W4_DIM) + w4 + chunk * ROWS_PER_THREAD * W4_DIM;
    const float4* __restrict__ src = x   + base;
    float4* __restrict__ dst       = out + base;

    // Load 8 rows (each warp-load covers 512B: 4 full 128B lines).
    float4 v[ROWS_PER_THREAD];
#pragma unroll
    for (int i = 0; i < ROWS_PER_THREAD; i++) {
        v[i] = __ldcs(src + i * W4_DIM);
    }

    // Local inclusive prefix max within the chunk (per float lane).
#pragma unroll
    for (int i = 1; i < ROWS_PER_THREAD; i++) {
        v[i] = fmax4(v[i], v[i - 1]);
    }

    // Block-level inclusive max-scan over chunk totals.
    __shared__ float4 s[CHUNKS][COLS4_PER_BLOCK];   // 16 KB
    const float4 NEG = make_float4(-CUDART_INF_F, -CUDART_INF_F,
                                   -CUDART_INF_F, -CUDART_INF_F);
    float4 t = v[ROWS_PER_THREAD - 1];
    s[chunk][c] = t;
    __syncthreads();

#pragma unroll
    for (int d = 1; d < CHUNKS; d <<= 1) {
        float4 o = (chunk >= d) ? s[chunk - d][c] : NEG;
        __syncthreads();
        t = fmax4(t, o);
        s[chunk][c] = t;
        __syncthreads();
    }

    // Exclusive carry from preceding chunks.
    const float4 carry = (chunk > 0) ? s[chunk - 1][c] : NEG;

    // Apply carry and store (streaming).
#pragma unroll
    for (int i = 0; i < ROWS_PER_THREAD; i++) {
        __stcs(dst + i * W4_DIM, fmax4(v[i], carry));
    }
}

extern "C" void kernel_launch(void* const* d_in, const int* in_sizes, int n_in,
                              void* d_out, int out_size) {
    const float4* x = (const float4*)d_in[0];
    float4* out = (float4*)d_out;

    const int total_cols4 = 32 * W4_DIM;                       // 8192
    const int grid = total_cols4 / COLS4_PER_BLOCK;            // 1024
    cummax_kernel<<<grid, 1024>>>(x, out);
}

// round 3
// speedup vs baseline: 1.3163x; 1.3163x over previous
#include <cuda_runtime.h>
#include <math_constants.h>

// Prefix-max (cumulative max) along H for x of shape (B=32, C=1, H=1024, W=1024), fp32.
// Layout: x[(b*H + h)*W + w]. 32768 independent columns (b,w), scan length H=1024.
//
// Tile: 512-thread block owns 16 consecutive float-columns x full H (2 CTAs/SM).
//   thread t: c = t & 15, chunk = t >> 4 (32 chunks of 32 rows).
//   Phase 1: 32 coalesced scalar loads -> registers, local prefix-max.
//   Phase 2: chunk totals -> smem (1 barrier); warp k shuffle-scans column k
//            (5 shfl rounds, no barriers); write back (1 barrier).
//   Phase 3: apply exclusive carry, 32 coalesced stores.
// Only 2 block barriers total; co-resident CTA overlaps scan with memory.

#define H_DIM 1024
#define W_DIM 1024
#define COLS_PER_BLOCK 16
#define CHUNKS 32
#define ROWS_PER_THREAD 32   // H_DIM / CHUNKS

__global__ __launch_bounds__(512, 2)
void cummax_kernel(const float* __restrict__ x, float* __restrict__ out) {
    const int tid   = threadIdx.x;
    const int c     = tid & (COLS_PER_BLOCK - 1);   // 0..15
    const int chunk = tid >> 4;                     // 0..31
    const int wid   = tid >> 5;                     // 0..15
    const int lane  = tid & 31;

    const int col = blockIdx.x * COLS_PER_BLOCK + c;  // 0..32767 (1024 % 16 == 0: no b straddle)
    const int b   = col >> 10;
    const int w   = col & (W_DIM - 1);

    const int base = b * (H_DIM * W_DIM) + w + chunk * ROWS_PER_THREAD * W_DIM;
    const float* __restrict__ src = x   + base;
    float* __restrict__ dst       = out + base;

    // Phase 1: load 32 rows (coalesced: warp covers 2 rows x 64B fully-used segments).
    float v[ROWS_PER_THREAD];
#pragma unroll
    for (int i = 0; i < ROWS_PER_THREAD; i++) {
        v[i] = src[i * W_DIM];
    }
#pragma unroll
    for (int i = 1; i < ROWS_PER_THREAD; i++) {
        v[i] = fmaxf(v[i], v[i - 1]);
    }

    // Phase 2: cross-chunk inclusive max-scan of totals, via warp shuffles.
    __shared__ float s[CHUNKS][COLS_PER_BLOCK + 1];   // pad -> conflict-free transposed access
    s[chunk][c] = v[ROWS_PER_THREAD - 1];
    __syncthreads();

    // Warp `wid` scans column `wid`: lane = chunk index.
    {
        float t = s[lane][wid];
#pragma unroll
        for (int d = 1; d < 32; d <<= 1) {
            float o = __shfl_up_sync(0xFFFFFFFFu, t, d);
            if (lane >= d) t = fmaxf(t, o);
        }
        s[lane][wid] = t;
    }
    __syncthreads();

    // Phase 3: exclusive carry, apply, store.
    const float carry = (chunk > 0) ? s[chunk - 1][c] : -CUDART_INF_F;
#pragma unroll
    for (int i = 0; i < ROWS_PER_THREAD; i++) {
        dst[i * W_DIM] = fmaxf(v[i], carry);
    }
}

extern "C" void kernel_launch(void* const* d_in, const int* in_sizes, int n_in,
                              void* d_out, int out_size) {
    const float* x = (const float*)d_in[0];
    float* out = (float*)d_out;

    const int total_cols = 32 * W_DIM;                        // 32768
    const int grid = total_cols / COLS_PER_BLOCK;             // 2048
    cummax_kernel<<<grid, 512>>>(x, out);
}